// round 13
// baseline (speedup 1.0000x reference)
#include <cuda_runtime.h>
#include <cuda_bf16.h>
#include <cstdint>

// B=1024, S=200, D=64, C=256
// Inputs: rq_item_embeddings f32 [B,S,D], labels i32 [B,S], attention_mask i32 [B,S]
// Output (float32, concatenated):
//   [0 .. B*C*D)             cluster_emb
//   [B*C*D .. +B*C*S)        cluster_mask (0.0f/1.0f)
//
// Grid = B*8: each CTA owns one batch b and a 32-cluster range.
// Mask zero-fill goes through cp.async.bulk (TMA bulk store) from a 4 KB
// zeroed smem buffer -> bypasses the L1tex/STG wavefront path. Bucket
// scatter overlaps the TMA flight; ones-writes ordered by wait_group+barrier.

namespace {
constexpr int B = 1024;
constexpr int S = 200;
constexpr int D = 64;
constexpr int C = 256;
constexpr int SPLIT = 8;
constexpr int CPART = C / SPLIT;       // 32 clusters per CTA
constexpr int ZBUF_BYTES = 4096;       // smem zero tile
constexpr int SLAB_BYTES = CPART * S * 4;   // 25600 per CTA
}

__global__ __launch_bounds__(256) void s3rec_fused_kernel(
    const float* __restrict__ x,       // [B,S,D]
    const int*   __restrict__ labels,  // [B,S]
    const int*   __restrict__ amask,   // [B,S]
    float*       __restrict__ out)
{
    __shared__ __align__(16) float zbuf[ZBUF_BYTES / 4];   // 4 KB zeros
    __shared__ int cnt[CPART];                             // per-cluster count
    __shared__ unsigned char bucket[CPART][S];             // s-indices, 6.4 KB

    const int b    = blockIdx.x >> 3;
    const int part = blockIdx.x & 7;
    const int tid  = threadIdx.x;
    const int w    = tid >> 5;
    const int lane = tid & 31;
    const int cBase = part * CPART;

    float* maskOutP = out + (size_t)B * C * D
                          + (size_t)b * C * S
                          + (size_t)cBase * S;

    // ---- Phase 0: zero smem tile + parallel label load ----------------
    reinterpret_cast<float4*>(zbuf)[tid] = make_float4(0.f, 0.f, 0.f, 0.f);
    int myLab = -1;
    if (tid < S) {
        int m = __ldg(amask + b * S + tid);
        myLab = m ? __ldg(labels + b * S + tid) : -1;
    }
    if (tid < CPART) cnt[tid] = 0;
    __syncthreads();

    // ---- Phase 1a: one thread launches the bulk zero stores -----------
    if (tid == 0) {
        asm volatile("fence.proxy.async.shared::cta;" ::: "memory");
        uint32_t saddr;
        asm("{ .reg .u64 t; cvta.to.shared.u64 t, %1; cvt.u32.u64 %0, t; }"
            : "=r"(saddr) : "l"(zbuf));
        char* g = reinterpret_cast<char*>(maskOutP);
        #pragma unroll
        for (int off = 0; off + ZBUF_BYTES <= SLAB_BYTES; off += ZBUF_BYTES) {
            asm volatile(
                "cp.async.bulk.global.shared::cta.bulk_group [%0], [%1], %2;"
                :: "l"(g + off), "r"(saddr), "r"(ZBUF_BYTES) : "memory");
        }
        {   // tail: 25600 - 6*4096 = 1024 bytes
            constexpr int TAIL = SLAB_BYTES - (SLAB_BYTES / ZBUF_BYTES) * ZBUF_BYTES;
            if (TAIL > 0)
                asm volatile(
                    "cp.async.bulk.global.shared::cta.bulk_group [%0], [%1], %2;"
                    :: "l"(g + (SLAB_BYTES - TAIL)), "r"(saddr), "r"(TAIL)
                    : "memory");
        }
        asm volatile("cp.async.bulk.commit_group;" ::: "memory");
    }

    // ---- Phase 1b: bucket scatter (overlaps the TMA flight) -----------
    {
        const int cl = myLab - cBase;
        if (cl >= 0 && cl < CPART) {
            int p = atomicAdd(&cnt[cl], 1);
            bucket[cl][p] = (unsigned char)tid;
        }
    }

    // ---- Drain bulk stores, then ones-writes may land -----------------
    if (tid == 0)
        asm volatile("cp.async.bulk.wait_group 0;" ::: "memory");
    __syncthreads();

    {
        const int cl = myLab - cBase;
        if (cl >= 0 && cl < CPART)
            maskOutP[cl * S + tid] = 1.0f;   // after zero-fill completion
    }

    // ---- Phase 2: gather; half-warp per cluster, float4 lanes ---------
    {
        const float* xb = x + (size_t)b * S * D;
        float* embOut   = out + (size_t)b * C * D;
        const int hw  = lane >> 4;
        const int l16 = lane & 15;

        #pragma unroll
        for (int pass = 0; pass < CPART / 16; pass++) {   // 2 passes
            const int cLocal = pass * 16 + w * 2 + hw;
            const int k = cnt[cLocal];
            float4 acc = make_float4(0.f, 0.f, 0.f, 0.f);
            if (k > 0) {
                int sCur = bucket[cLocal][0];
                for (int j = 0; j < k; j++) {
                    const int sNext = (j + 1 < k) ? (int)bucket[cLocal][j + 1] : 0;
                    const float4 vv =
                        reinterpret_cast<const float4*>(xb + sCur * D)[l16];
                    acc.x += vv.x; acc.y += vv.y; acc.z += vv.z; acc.w += vv.w;
                    sCur = sNext;
                }
                const float inv = 1.0f / (float)k;
                acc.x *= inv; acc.y *= inv; acc.z *= inv; acc.w *= inv;
            }
            __stcs(reinterpret_cast<float4*>(embOut + (cBase + cLocal) * D) + l16, acc);
        }
    }
}

extern "C" void kernel_launch(void* const* d_in, const int* in_sizes, int n_in,
                              void* d_out, int out_size)
{
    const float* x      = (const float*)d_in[0];
    const int*   labels = (const int*)d_in[1];
    const int*   amask  = (const int*)d_in[2];
    float*       out    = (float*)d_out;

    s3rec_fused_kernel<<<B * SPLIT, 256>>>(x, labels, amask, out);
}

// round 14
// speedup vs baseline: 1.0118x; 1.0118x over previous
#include <cuda_runtime.h>
#include <cuda_bf16.h>
#include <cstdint>

// B=1024, S=200, D=64, C=256
// Inputs: rq_item_embeddings f32 [B,S,D], labels i32 [B,S], attention_mask i32 [B,S]
// Output (float32, concatenated):
//   [0 .. B*C*D)             cluster_emb
//   [B*C*D .. +B*C*S)        cluster_mask (0.0f/1.0f)
//
// Grid = B*8: each CTA owns one batch b and a 32-cluster range.
// R10 structure (best known): zero-fill + uint8 buckets via one atomic,
// 2 block barriers. This round adds streaming-evict loads (__ldcs) on the
// once-read x data to protect L2 for the dominant store stream.

namespace {
constexpr int B = 1024;
constexpr int S = 200;
constexpr int D = 64;
constexpr int C = 256;
constexpr int SPLIT = 8;
constexpr int CPART = C / SPLIT;      // 32 clusters per CTA
}

__global__ __launch_bounds__(256) void s3rec_fused_kernel(
    const float* __restrict__ x,       // [B,S,D]
    const int*   __restrict__ labels,  // [B,S]
    const int*   __restrict__ amask,   // [B,S]
    float*       __restrict__ out)
{
    __shared__ int cnt[CPART];                    // per-local-cluster count
    __shared__ unsigned char bucket[CPART][S];    // member s-indices, 6.4 KB

    const int b    = blockIdx.x >> 3;
    const int part = blockIdx.x & 7;    // cluster octant
    const int tid  = threadIdx.x;
    const int w    = tid >> 5;
    const int lane = tid & 31;
    const int cBase = part * CPART;

    float* maskOutP = out + (size_t)B * C * D
                          + (size_t)b * C * S
                          + (size_t)cBase * S;

    // ---- Phase 0: wide label load + counts zero + mask zero-fill ------
    int myLab = -1;
    if (tid < S) {
        int m = __ldg(amask + b * S + tid);       // reused by 8 sibling CTAs
        myLab = m ? __ldg(labels + b * S + tid) : -1;
    }
    if (tid < CPART) cnt[tid] = 0;

    {
        const float4 z4 = make_float4(0.f, 0.f, 0.f, 0.f);
        float4* mq = reinterpret_cast<float4*>(maskOutP);
        constexpr int NQ = CPART * S / 4;   // 1600 quads, 6.25/thread
        #pragma unroll 7
        for (int i = tid; i < NQ; i += 256)
            __stcs(mq + i, z4);
    }
    __syncthreads();

    // ---- Phase 1: bucket scatter + ones write (one atomic does both) --
    {
        const int cl = myLab - cBase;
        if (cl >= 0 && cl < CPART) {
            int p = atomicAdd(&cnt[cl], 1);
            bucket[cl][p] = (unsigned char)tid;
            maskOutP[cl * S + tid] = 1.0f;   // ordered after zero-fill barrier
        }
    }
    __syncthreads();

    // ---- Phase 2: gather; half-warp per cluster, float4 lanes ---------
    // Each warp handles 2 clusters per pass (lanes 0-15 / 16-31),
    // 16 lanes x float4 = one D row. 2 passes x 16 = 32 clusters.
    {
        const float* xb = x + (size_t)b * S * D;
        float* embOut   = out + (size_t)b * C * D;
        const int hw  = lane >> 4;          // half-warp id (0/1)
        const int l16 = lane & 15;

        #pragma unroll
        for (int pass = 0; pass < CPART / 16; pass++) {   // 2 passes
            const int cLocal = pass * 16 + w * 2 + hw;
            const int k = cnt[cLocal];
            float4 acc = make_float4(0.f, 0.f, 0.f, 0.f);
            if (k > 0) {
                int sCur = bucket[cLocal][0];
                for (int j = 0; j < k; j++) {
                    const int sNext = (j + 1 < k) ? (int)bucket[cLocal][j + 1] : 0;
                    const float4 vv = __ldcs(
                        reinterpret_cast<const float4*>(xb + sCur * D) + l16);
                    acc.x += vv.x; acc.y += vv.y; acc.z += vv.z; acc.w += vv.w;
                    sCur = sNext;
                }
                const float inv = 1.0f / (float)k;
                acc.x *= inv; acc.y *= inv; acc.z *= inv; acc.w *= inv;
            }
            __stcs(reinterpret_cast<float4*>(embOut + (cBase + cLocal) * D) + l16, acc);
        }
    }
}

extern "C" void kernel_launch(void* const* d_in, const int* in_sizes, int n_in,
                              void* d_out, int out_size)
{
    const float* x      = (const float*)d_in[0];
    const int*   labels = (const int*)d_in[1];
    const int*   amask  = (const int*)d_in[2];
    float*       out    = (float*)d_out;

    s3rec_fused_kernel<<<B * SPLIT, 256>>>(x, labels, amask, out);
}

// round 15
// speedup vs baseline: 1.0885x; 1.0758x over previous
#include <cuda_runtime.h>
#include <cuda_bf16.h>
#include <cstdint>

// B=1024, S=200, D=64, C=256
// Inputs: rq_item_embeddings f32 [B,S,D], labels i32 [B,S], attention_mask i32 [B,S]
// Output (float32, concatenated):
//   [0 .. B*C*D)             cluster_emb
//   [B*C*D .. +B*C*S)        cluster_mask (0.0f/1.0f)
//
// FINAL (R10 config, best measured 47.1us, DRAM ~64%):
// Grid = B*8: each CTA owns one batch b and a 32-cluster range.
// Direct smem bucketing (uint8 s-indices): one atomicAdd yields both count
// and slot, 2 block barriers total, ~7.5 KB smem -> ~80% occupancy.
// Mask = streaming zero-fill + sparse ones scatter (beats inline compute:
// the double-write coalesces in L2; inline compute costs issue slots).

namespace {
constexpr int B = 1024;
constexpr int S = 200;
constexpr int D = 64;
constexpr int C = 256;
constexpr int SPLIT = 8;
constexpr int CPART = C / SPLIT;      // 32 clusters per CTA
}

__global__ __launch_bounds__(256) void s3rec_fused_kernel(
    const float* __restrict__ x,       // [B,S,D]
    const int*   __restrict__ labels,  // [B,S]
    const int*   __restrict__ amask,   // [B,S]
    float*       __restrict__ out)
{
    __shared__ int cnt[CPART];                    // per-local-cluster count
    __shared__ unsigned char bucket[CPART][S];    // member s-indices, 6.4 KB

    const int b    = blockIdx.x >> 3;
    const int part = blockIdx.x & 7;    // cluster octant
    const int tid  = threadIdx.x;
    const int w    = tid >> 5;
    const int lane = tid & 31;
    const int cBase = part * CPART;

    float* maskOutP = out + (size_t)B * C * D
                          + (size_t)b * C * S
                          + (size_t)cBase * S;

    // ---- Phase 0: wide label load + counts zero + mask zero-fill ------
    int myLab = -1;
    if (tid < S) {
        int m = __ldg(amask + b * S + tid);
        myLab = m ? __ldg(labels + b * S + tid) : -1;
    }
    if (tid < CPART) cnt[tid] = 0;

    {
        const float4 z4 = make_float4(0.f, 0.f, 0.f, 0.f);
        float4* mq = reinterpret_cast<float4*>(maskOutP);
        constexpr int NQ = CPART * S / 4;   // 1600 quads, 6.25/thread
        #pragma unroll 7
        for (int i = tid; i < NQ; i += 256)
            __stcs(mq + i, z4);
    }
    __syncthreads();

    // ---- Phase 1: bucket scatter + ones write (one atomic does both) --
    {
        const int cl = myLab - cBase;
        if (cl >= 0 && cl < CPART) {
            int p = atomicAdd(&cnt[cl], 1);
            bucket[cl][p] = (unsigned char)tid;
            maskOutP[cl * S + tid] = 1.0f;   // ordered after zero-fill barrier
        }
    }
    __syncthreads();

    // ---- Phase 2: gather; half-warp per cluster, float4 lanes ---------
    // Each warp handles 2 clusters per pass (lanes 0-15 / 16-31),
    // 16 lanes x float4 = one D row. 2 passes x 16 = 32 clusters.
    {
        const float* xb = x + (size_t)b * S * D;
        float* embOut   = out + (size_t)b * C * D;
        const int hw  = lane >> 4;          // half-warp id (0/1)
        const int l16 = lane & 15;

        #pragma unroll
        for (int pass = 0; pass < CPART / 16; pass++) {   // 2 passes
            const int cLocal = pass * 16 + w * 2 + hw;
            const int k = cnt[cLocal];
            float4 acc = make_float4(0.f, 0.f, 0.f, 0.f);
            if (k > 0) {
                int sCur = bucket[cLocal][0];
                for (int j = 0; j < k; j++) {
                    const int sNext = (j + 1 < k) ? (int)bucket[cLocal][j + 1] : 0;
                    const float4 vv =
                        reinterpret_cast<const float4*>(xb + sCur * D)[l16];
                    acc.x += vv.x; acc.y += vv.y; acc.z += vv.z; acc.w += vv.w;
                    sCur = sNext;
                }
                const float inv = 1.0f / (float)k;
                acc.x *= inv; acc.y *= inv; acc.z *= inv; acc.w *= inv;
            }
            __stcs(reinterpret_cast<float4*>(embOut + (cBase + cLocal) * D) + l16, acc);
        }
    }
}

extern "C" void kernel_launch(void* const* d_in, const int* in_sizes, int n_in,
                              void* d_out, int out_size)
{
    const float* x      = (const float*)d_in[0];
    const int*   labels = (const int*)d_in[1];
    const int*   amask  = (const int*)d_in[2];
    float*       out    = (float*)d_out;

    s3rec_fused_kernel<<<B * SPLIT, 256>>>(x, labels, amask, out);
}